// round 1
// baseline (speedup 1.0000x reference)
#include <cuda_runtime.h>
#include <math.h>
#include <float.h>

#define N_ROWS   16384
#define DIM      7168
#define N_EXP    256
#define N_GROUPS 8
#define N_TOPK_GROUP 4
#define TOPK     8
#define ROUTED_SCALE 2.5f

// scratch: original = sigmoid(x @ W^T), [N_ROWS, N_EXP] fp32 (16.7 MB)
__device__ float g_orig[(size_t)N_ROWS * N_EXP];

// ---------------------------------------------------------------------------
// GEMM + sigmoid epilogue.  BM=128, BN=128, BK=16, 256 threads, 8x8 microtile.
// x: [N_ROWS, DIM] row-major, W: [N_EXP, DIM] row-major (both K-major).
// ---------------------------------------------------------------------------
__global__ __launch_bounds__(256, 2)
void gemm_sigmoid_kernel(const float* __restrict__ x, const float* __restrict__ W) {
    const int BM = 128, BN = 128, BK = 16;
    __shared__ float As[BK][BM];   // transposed: As[k][m]
    __shared__ float Bs[BK][BN];   // transposed: Bs[k][n]

    const int tid = threadIdx.x;
    const int m0  = blockIdx.x * BM;
    const int n0  = blockIdx.y * BN;
    const int tm  = tid >> 4;       // 0..15
    const int tn  = tid & 15;       // 0..15

    float acc[8][8];
#pragma unroll
    for (int i = 0; i < 8; i++)
#pragma unroll
        for (int j = 0; j < 8; j++) acc[i][j] = 0.f;

    // load mapping: 128x16 floats = 512 float4; 256 threads -> 2 float4 each
    const int lrow = tid >> 2;          // 0..63
    const int lcol = (tid & 3) << 2;    // 0,4,8,12

    for (int k0 = 0; k0 < DIM; k0 += BK) {
#pragma unroll
        for (int half = 0; half < 2; half++) {
            const int r = lrow + half * 64;
            float4 v = *reinterpret_cast<const float4*>(
                &x[(size_t)(m0 + r) * DIM + k0 + lcol]);
            As[lcol + 0][r] = v.x;
            As[lcol + 1][r] = v.y;
            As[lcol + 2][r] = v.z;
            As[lcol + 3][r] = v.w;
        }
#pragma unroll
        for (int half = 0; half < 2; half++) {
            const int r = lrow + half * 64;
            float4 v = *reinterpret_cast<const float4*>(
                &W[(size_t)(n0 + r) * DIM + k0 + lcol]);
            Bs[lcol + 0][r] = v.x;
            Bs[lcol + 1][r] = v.y;
            Bs[lcol + 2][r] = v.z;
            Bs[lcol + 3][r] = v.w;
        }
        __syncthreads();

#pragma unroll
        for (int k = 0; k < BK; k++) {
            float4 a0 = *reinterpret_cast<const float4*>(&As[k][tm * 8]);
            float4 a1 = *reinterpret_cast<const float4*>(&As[k][tm * 8 + 4]);
            float4 b0 = *reinterpret_cast<const float4*>(&Bs[k][tn * 8]);
            float4 b1 = *reinterpret_cast<const float4*>(&Bs[k][tn * 8 + 4]);
            float a[8] = {a0.x, a0.y, a0.z, a0.w, a1.x, a1.y, a1.z, a1.w};
            float b[8] = {b0.x, b0.y, b0.z, b0.w, b1.x, b1.y, b1.z, b1.w};
#pragma unroll
            for (int i = 0; i < 8; i++)
#pragma unroll
                for (int j = 0; j < 8; j++)
                    acc[i][j] = fmaf(a[i], b[j], acc[i][j]);
        }
        __syncthreads();
    }

#pragma unroll
    for (int i = 0; i < 8; i++) {
        const int row = m0 + tm * 8 + i;
#pragma unroll
        for (int j = 0; j < 8; j++) {
            const int col = n0 + tn * 8 + j;
            float o = 1.0f / (1.0f + expf(-acc[i][j]));
            g_orig[(size_t)row * N_EXP + col] = o;
        }
    }
}

// ---------------------------------------------------------------------------
// Routing: one block (256 threads) per row. warp == group (8 groups x 32).
// ---------------------------------------------------------------------------
__global__ __launch_bounds__(256)
void routing_kernel(const float* __restrict__ bias,
                    float* __restrict__ out_w, float* __restrict__ out_i) {
    const int row  = blockIdx.x;
    const int e    = threadIdx.x;
    const int lane = e & 31;
    const int grp  = e >> 5;

    const float orig = g_orig[(size_t)row * N_EXP + e];
    const float s    = orig + bias[e];

    // --- top-2 sum within group (one warp per group) ---
    float m1 = s;
#pragma unroll
    for (int off = 16; off; off >>= 1)
        m1 = fmaxf(m1, __shfl_xor_sync(0xffffffffu, m1, off));
    unsigned ballot = __ballot_sync(0xffffffffu, s == m1);
    int firstlane = __ffs(ballot) - 1;
    float v2 = (lane == firstlane) ? -FLT_MAX : s;
    float m2 = v2;
#pragma unroll
    for (int off = 16; off; off >>= 1)
        m2 = fmaxf(m2, __shfl_xor_sync(0xffffffffu, m2, off));

    __shared__ float gscore[N_GROUPS];
    __shared__ int   keep[N_GROUPS];
    if (lane == 0) gscore[grp] = m1 + m2;
    if (e < N_GROUPS) keep[e] = 0;
    __syncthreads();

    // --- pick top-4 groups (serial, ties -> lower index, matches lax.top_k) ---
    if (e == 0) {
        float tmp[N_GROUPS];
#pragma unroll
        for (int g = 0; g < N_GROUPS; g++) tmp[g] = gscore[g];
        for (int t = 0; t < N_TOPK_GROUP; t++) {
            int best = 0;
            for (int g = 1; g < N_GROUPS; g++)
                if (tmp[g] > tmp[best]) best = g;
            keep[best] = 1;
            tmp[best] = -FLT_MAX;
        }
    }
    __syncthreads();

    float myv = keep[grp] ? s : -FLT_MAX;
    int   myi = e;

    __shared__ float red_v[8];
    __shared__ int   red_i[8];
    __shared__ float sel_w[TOPK];
    __shared__ int   sel_i[TOPK];

    // --- iterative block-wide top-8 (value desc, ties -> lower index) ---
    for (int t = 0; t < TOPK; t++) {
        float wv = myv; int wi = myi;
#pragma unroll
        for (int off = 16; off; off >>= 1) {
            float ov = __shfl_xor_sync(0xffffffffu, wv, off);
            int   oi = __shfl_xor_sync(0xffffffffu, wi, off);
            if (ov > wv || (ov == wv && oi < wi)) { wv = ov; wi = oi; }
        }
        if (lane == 0) { red_v[grp] = wv; red_i[grp] = wi; }
        __syncthreads();
        if (e == 0) {
            float bv = red_v[0]; int bi = red_i[0];
#pragma unroll
            for (int g = 1; g < 8; g++)
                if (red_v[g] > bv || (red_v[g] == bv && red_i[g] < bi)) {
                    bv = red_v[g]; bi = red_i[g];
                }
            sel_i[t] = bi;
            sel_w[t] = g_orig[(size_t)row * N_EXP + bi];  // weight from ORIGINAL (no bias)
        }
        __syncthreads();
        if (e == sel_i[t]) myv = -FLT_MAX;
        __syncthreads();
    }

    if (e == 0) {
        float sum = 0.f;
#pragma unroll
        for (int t = 0; t < TOPK; t++) sum += sel_w[t];
        const float scl = ROUTED_SCALE / sum;
#pragma unroll
        for (int t = 0; t < TOPK; t++) {
            out_w[(size_t)row * TOPK + t] = sel_w[t] * scl;
            out_i[(size_t)row * TOPK + t] = (float)sel_i[t];
        }
    }
}

extern "C" void kernel_launch(void* const* d_in, const int* in_sizes, int n_in,
                              void* d_out, int out_size) {
    const float* x = (const float*)d_in[0];   // [16384, 7168]
    const float* W = (const float*)d_in[1];   // [256, 7168]
    const float* b = (const float*)d_in[2];   // [256]
    float* out = (float*)d_out;               // [N*8 weights][N*8 indices-as-float]

    dim3 grid(N_ROWS / 128, N_EXP / 128);
    gemm_sigmoid_kernel<<<grid, 256>>>(x, W);
    routing_kernel<<<N_ROWS, 256>>>(b, out, out + (size_t)N_ROWS * TOPK);
}